// round 1
// baseline (speedup 1.0000x reference)
#include <cuda_runtime.h>
#include <math.h>
#include <stdint.h>

// Problem constants
#define BB      16
#define LL      2048
#define DD      768
#define HH      12
#define NLAYER  4
#define FDIM    32
#define HDIM    64
#define NTOK    (BB * LL)            // 32768
#define ATTN_EPS 1e-6f
#define LN_EPS   1e-5f

// ---------------------------------------------------------------------------
// Scratch buffers (static __device__ — no runtime allocation)
// ---------------------------------------------------------------------------
__device__ float g_X [(size_t)NTOK * DD];   // residual stream
__device__ float g_Y [(size_t)NTOK * DD];   // attn/ffn outputs
__device__ float g_Q [(size_t)NTOK * DD];   // Q projection / FFN hidden (reused)
__device__ float g_K [(size_t)NTOK * DD];
__device__ float g_V [(size_t)NTOK * DD];
__device__ float g_PHQ[(size_t)NTOK * HH * FDIM];
__device__ float g_PHK[(size_t)NTOK * HH * FDIM];
__device__ float g_KV  [BB * HH * FDIM * HDIM];
__device__ float g_KSUM[BB * HH * FDIM];
__device__ float g_COS [LL * (HDIM / 2)];
__device__ float g_SIN [LL * (HDIM / 2)];

// ---------------------------------------------------------------------------
// Embedding gather: X[n, :] = tok_emb[idx[n], :]
// ---------------------------------------------------------------------------
__global__ __launch_bounds__(256) void embed_kernel(
    const int* __restrict__ idx, const float* __restrict__ emb,
    float* __restrict__ X)
{
    int i   = blockIdx.x * 256 + threadIdx.x;       // over NTOK*DD/4
    int tok = i / (DD / 4);
    int c4  = i % (DD / 4);
    const float4* src = (const float4*)(emb + (size_t)idx[tok] * DD);
    ((float4*)X)[i] = src[c4];
}

// ---------------------------------------------------------------------------
// Rotary cos/sin table (2048 positions x 32 freqs), double-precision trig
// ---------------------------------------------------------------------------
__global__ __launch_bounds__(256) void rope_table_kernel(
    float* __restrict__ cosT, float* __restrict__ sinT)
{
    int i = blockIdx.x * 256 + threadIdx.x;         // l*32 + j, 65536 total
    int j = i & 31;
    int l = i >> 5;
    double inv = pow(10000.0, -(double)(2 * j) / (double)HDIM);
    double fr  = (double)l * inv;
    cosT[i] = (float)cos(fr);
    sinT[i] = (float)sin(fr);
}

// ---------------------------------------------------------------------------
// Rotary applied in-place to Q and K
// ---------------------------------------------------------------------------
__global__ __launch_bounds__(256) void rotary_kernel(
    float* __restrict__ Q, float* __restrict__ K,
    const float* __restrict__ cosT, const float* __restrict__ sinT)
{
    int i   = blockIdx.x * 256 + threadIdx.x;       // over NTOK*HH*32
    int j   = i & 31;
    int rem = i >> 5;
    int h   = rem % HH;
    int n   = rem / HH;
    int l   = n & (LL - 1);
    float c = cosT[l * 32 + j];
    float s = sinT[l * 32 + j];
    size_t base = (size_t)n * DD + h * HDIM + j;
    float x1, x2;
    x1 = Q[base]; x2 = Q[base + 32];
    Q[base]      = x1 * c - x2 * s;
    Q[base + 32] = x2 * c + x1 * s;
    x1 = K[base]; x2 = K[base + 32];
    K[base]      = x1 * c - x2 * s;
    K[base + 32] = x2 * c + x1 * s;
}

// ---------------------------------------------------------------------------
// Feature map: PH[n,h,f] = relu( sum_d X[n, h*64+d] * omega[d,f] ) * mask?
// One thread per (n,h). omega (64x32) staged in smem, read as float4 over f.
// ---------------------------------------------------------------------------
__global__ __launch_bounds__(256) void phi_kernel(
    const float* __restrict__ X, const float* __restrict__ omega,
    const int* __restrict__ mask, float* __restrict__ PH)
{
    __shared__ float4 som[HDIM * FDIM / 4];          // [d*8 + f4]
    int tid = threadIdx.x;
    #pragma unroll
    for (int p = 0; p < 2; p++)
        som[tid + p * 256] = ((const float4*)omega)[tid + p * 256];
    __syncthreads();

    int id = blockIdx.x * 256 + tid;                 // (n,h) flat
    int n  = id / HH;
    int h  = id % HH;

    float q[HDIM];
    const float4* src = (const float4*)(X + (size_t)n * DD + h * HDIM);
    #pragma unroll
    for (int i = 0; i < HDIM / 4; i++) {
        float4 v = src[i];
        q[i * 4 + 0] = v.x; q[i * 4 + 1] = v.y;
        q[i * 4 + 2] = v.z; q[i * 4 + 3] = v.w;
    }
    float m = mask ? (float)mask[n] : 1.0f;

    float4* out = (float4*)(PH + (size_t)id * FDIM);
    #pragma unroll
    for (int f4 = 0; f4 < FDIM / 4; f4++) {
        float4 acc = make_float4(0.f, 0.f, 0.f, 0.f);
        #pragma unroll
        for (int d = 0; d < HDIM; d++) {
            float4 w = som[d * 8 + f4];
            acc.x += q[d] * w.x; acc.y += q[d] * w.y;
            acc.z += q[d] * w.z; acc.w += q[d] * w.w;
        }
        acc.x = fmaxf(acc.x, 0.f) * m; acc.y = fmaxf(acc.y, 0.f) * m;
        acc.z = fmaxf(acc.z, 0.f) * m; acc.w = fmaxf(acc.w, 0.f) * m;
        out[f4] = acc;
    }
}

// ---------------------------------------------------------------------------
// KV state: kv[b,h,f,d] = sum_l phk[b,l,h,f] * v[b,l,h,d]
//           ksum[b,h,f] = sum_l phk[b,l,h,f]
// One block (256 thr) per (b,h). Tiles of 32 tokens in smem.
// Thread (f = tid&31, dg = tid>>5) accumulates 8 d-values.
// ---------------------------------------------------------------------------
__global__ __launch_bounds__(256) void kv_kernel(
    const float* __restrict__ PHK, const float* __restrict__ V,
    float* __restrict__ KV, float* __restrict__ KSUM)
{
    __shared__ float sph[32 * FDIM];   // [r][f]
    __shared__ float sv [32 * HDIM];   // [r][d]
    int bh = blockIdx.x;
    int b  = bh / HH;
    int h  = bh % HH;
    int tid = threadIdx.x;
    int f  = tid & 31;
    int dg = tid >> 5;                  // 0..7 -> d = dg*8 .. dg*8+7
    float acc[8] = {0.f,0.f,0.f,0.f,0.f,0.f,0.f,0.f};
    float sacc = 0.f;

    int rA  = tid >> 3, cA = (tid & 7) * 4;     // phk tile load
    for (int l0 = 0; l0 < LL; l0 += 32) {
        *(float4*)&sph[rA * FDIM + cA] =
            *(const float4*)(PHK + ((size_t)(b * LL + l0 + rA) * HH + h) * FDIM + cA);
        #pragma unroll
        for (int p = 0; p < 2; p++) {
            int ii = tid + p * 256;
            int rr = ii >> 4, cc = (ii & 15) * 4;
            *(float4*)&sv[rr * HDIM + cc] =
                *(const float4*)(V + (size_t)(b * LL + l0 + rr) * DD + h * HDIM + cc);
        }
        __syncthreads();
        #pragma unroll 8
        for (int r = 0; r < 32; r++) {
            float ph = sph[r * FDIM + f];
            sacc += ph;
            float4 v0 = *(const float4*)&sv[r * HDIM + dg * 8];
            float4 v1 = *(const float4*)&sv[r * HDIM + dg * 8 + 4];
            acc[0] += ph * v0.x; acc[1] += ph * v0.y;
            acc[2] += ph * v0.z; acc[3] += ph * v0.w;
            acc[4] += ph * v1.x; acc[5] += ph * v1.y;
            acc[6] += ph * v1.z; acc[7] += ph * v1.w;
        }
        __syncthreads();
    }
    float* dst = KV + ((size_t)bh * FDIM + f) * HDIM + dg * 8;
    #pragma unroll
    for (int jj = 0; jj < 8; jj++) dst[jj] = acc[jj];
    if (dg == 0) KSUM[bh * FDIM + f] = sacc;
}

// ---------------------------------------------------------------------------
// Attention output: Y[n, h*64+d] = z * sum_f phq[n,h,f] * kv[b,h,f,d]
//   z = 1 / (sum_f phq[n,h,f]*ksum[b,h,f] + eps)
// Block = (chunk of 256 tokens, bh). KV tile + ksum staged in smem.
// ---------------------------------------------------------------------------
__global__ __launch_bounds__(256) void attn_out_kernel(
    const float* __restrict__ PHQ, const float* __restrict__ KV,
    const float* __restrict__ KSUM, float* __restrict__ Y)
{
    __shared__ float4 skv[FDIM * HDIM / 4];   // [f*16 + d4]
    __shared__ float  sks[FDIM];
    int bh  = blockIdx.y;
    int tid = threadIdx.x;
    #pragma unroll
    for (int p = 0; p < 2; p++)
        skv[tid + p * 256] = ((const float4*)(KV + (size_t)bh * FDIM * HDIM))[tid + p * 256];
    if (tid < FDIM) sks[tid] = KSUM[bh * FDIM + tid];
    __syncthreads();

    int b = bh / HH, h = bh % HH;
    size_t n = (size_t)b * LL + blockIdx.x * 256 + tid;

    float ph[FDIM];
    const float4* src = (const float4*)(PHQ + (n * HH + h) * FDIM);
    #pragma unroll
    for (int i = 0; i < FDIM / 4; i++) {
        float4 v = src[i];
        ph[i * 4 + 0] = v.x; ph[i * 4 + 1] = v.y;
        ph[i * 4 + 2] = v.z; ph[i * 4 + 3] = v.w;
    }
    float den = ATTN_EPS;
    #pragma unroll
    for (int fI = 0; fI < FDIM; fI++) den += ph[fI] * sks[fI];
    float z = 1.0f / den;

    float4* outp = (float4*)(Y + n * DD + h * HDIM);
    #pragma unroll
    for (int d4 = 0; d4 < HDIM / 4; d4++) {
        float4 acc = make_float4(0.f, 0.f, 0.f, 0.f);
        #pragma unroll
        for (int fI = 0; fI < FDIM; fI++) {
            float4 kvv = skv[fI * 16 + d4];
            acc.x += ph[fI] * kvv.x; acc.y += ph[fI] * kvv.y;
            acc.z += ph[fI] * kvv.z; acc.w += ph[fI] * kvv.w;
        }
        acc.x *= z; acc.y *= z; acc.z *= z; acc.w *= z;
        outp[d4] = acc;
    }
}

// ---------------------------------------------------------------------------
// SGEMM: C[M,N] = act(A[M,K] @ W[K,N] + bias) (+ R)   — fp32, 64x64x16 tiles
// act: 0 = none, 1 = exact GELU (applied before residual add)
// ---------------------------------------------------------------------------
#define BM 64
#define BN 64
#define BK 16
__global__ __launch_bounds__(256) void sgemm_kernel(
    const float* __restrict__ A, const float* __restrict__ W,
    const float* __restrict__ bias, const float* __restrict__ R,
    float* __restrict__ C, int M, int N, int K, int act)
{
    __shared__ float As[BK][BM];   // transposed A tile
    __shared__ float Bs[BK][BN];
    int tid = threadIdx.x;
    int tx  = tid & 15, ty = tid >> 4;
    size_t rowBase = (size_t)blockIdx.y * BM;
    size_t colBase = (size_t)blockIdx.x * BN;

    int ar = tid >> 2,  ac = (tid & 3) * 4;       // A tile: 64 rows x 16 cols
    int br = tid >> 4,  bc = (tid & 15) * 4;      // B tile: 16 rows x 64 cols

    float acc[4][4];
    #pragma unroll
    for (int i = 0; i < 4; i++)
        #pragma unroll
        for (int j = 0; j < 4; j++) acc[i][j] = 0.f;

    for (int k0 = 0; k0 < K; k0 += BK) {
        float4 a = *(const float4*)(A + (rowBase + ar) * K + k0 + ac);
        As[ac + 0][ar] = a.x; As[ac + 1][ar] = a.y;
        As[ac + 2][ar] = a.z; As[ac + 3][ar] = a.w;
        *(float4*)&Bs[br][bc] = *(const float4*)(W + (size_t)(k0 + br) * N + colBase + bc);
        __syncthreads();
        #pragma unroll
        for (int kk = 0; kk < BK; kk++) {
            float4 av = *(const float4*)&As[kk][ty * 4];
            float4 bv = *(const float4*)&Bs[kk][tx * 4];
            float ra[4] = {av.x, av.y, av.z, av.w};
            float rb[4] = {bv.x, bv.y, bv.z, bv.w};
            #pragma unroll
            for (int i = 0; i < 4; i++)
                #pragma unroll
                for (int j = 0; j < 4; j++)
                    acc[i][j] += ra[i] * rb[j];
        }
        __syncthreads();
    }

    size_t col = colBase + tx * 4;
    float4 b4 = *(const float4*)(bias + col);
    #pragma unroll
    for (int i = 0; i < 4; i++) {
        size_t row = rowBase + ty * 4 + i;
        float4 v;
        v.x = acc[i][0] + b4.x; v.y = acc[i][1] + b4.y;
        v.z = acc[i][2] + b4.z; v.w = acc[i][3] + b4.w;
        if (act == 1) {
            v.x = 0.5f * v.x * (1.f + erff(v.x * 0.70710678118654752f));
            v.y = 0.5f * v.y * (1.f + erff(v.y * 0.70710678118654752f));
            v.z = 0.5f * v.z * (1.f + erff(v.z * 0.70710678118654752f));
            v.w = 0.5f * v.w * (1.f + erff(v.w * 0.70710678118654752f));
        }
        if (R) {
            float4 r4 = *(const float4*)(R + row * N + col);
            v.x += r4.x; v.y += r4.y; v.z += r4.z; v.w += r4.w;
        }
        *(float4*)(C + row * N + col) = v;
    }
}

// ---------------------------------------------------------------------------
// LayerNorm: out[row,:] = (x - mu) * rsqrt(var + 1e-5) * g + b
// One block per row; row staged in smem (safe for in-place).
// ---------------------------------------------------------------------------
__global__ __launch_bounds__(256) void ln_kernel(
    const float* __restrict__ in, const float* __restrict__ g,
    const float* __restrict__ b, float* __restrict__ out)
{
    __shared__ float sx[DD];
    __shared__ float red[256];
    size_t row = blockIdx.x;
    int tid = threadIdx.x;
    const float* ip = in + row * DD;

    float s = 0.f;
    #pragma unroll
    for (int j = tid; j < DD; j += 256) { float v = ip[j]; sx[j] = v; s += v; }
    red[tid] = s; __syncthreads();
    #pragma unroll
    for (int off = 128; off > 0; off >>= 1) {
        if (tid < off) red[tid] += red[tid + off];
        __syncthreads();
    }
    float mu = red[0] * (1.0f / DD);
    __syncthreads();

    float s2 = 0.f;
    #pragma unroll
    for (int j = tid; j < DD; j += 256) { float d = sx[j] - mu; s2 += d * d; }
    red[tid] = s2; __syncthreads();
    #pragma unroll
    for (int off = 128; off > 0; off >>= 1) {
        if (tid < off) red[tid] += red[tid + off];
        __syncthreads();
    }
    float rstd = rsqrtf(red[0] * (1.0f / DD) + LN_EPS);

    #pragma unroll
    for (int j = tid; j < DD; j += 256)
        out[row * DD + j] = (sx[j] - mu) * rstd * g[j] + b[j];
}

// ---------------------------------------------------------------------------
// Host orchestration
// ---------------------------------------------------------------------------
extern "C" void kernel_launch(void* const* d_in, const int* in_sizes, int n_in,
                              void* d_out, int out_size)
{
    const int*   idx     = (const int*)  d_in[0];
    const int*   mask    = (const int*)  d_in[1];
    const float* tok_emb = (const float*)d_in[2];
    const float* Wq = (const float*)d_in[3];
    const float* bq = (const float*)d_in[4];
    const float* Wk = (const float*)d_in[5];
    const float* bk = (const float*)d_in[6];
    const float* Wv = (const float*)d_in[7];
    const float* bv = (const float*)d_in[8];
    const float* Wo = (const float*)d_in[9];
    const float* bo = (const float*)d_in[10];
    const float* om = (const float*)d_in[11];
    const float* W1 = (const float*)d_in[12];
    const float* b1 = (const float*)d_in[13];
    const float* W2 = (const float*)d_in[14];
    const float* b2 = (const float*)d_in[15];
    const float* g1 = (const float*)d_in[16];
    const float* be1= (const float*)d_in[17];
    const float* g2 = (const float*)d_in[18];
    const float* be2= (const float*)d_in[19];
    const float* gf = (const float*)d_in[20];
    const float* bf = (const float*)d_in[21];
    float* out = (float*)d_out;

    float *X, *Y, *Q, *K, *V, *PHQ, *PHK, *KV, *KSUM, *COS, *SIN;
    cudaGetSymbolAddress((void**)&X,    g_X);
    cudaGetSymbolAddress((void**)&Y,    g_Y);
    cudaGetSymbolAddress((void**)&Q,    g_Q);
    cudaGetSymbolAddress((void**)&K,    g_K);
    cudaGetSymbolAddress((void**)&V,    g_V);
    cudaGetSymbolAddress((void**)&PHQ,  g_PHQ);
    cudaGetSymbolAddress((void**)&PHK,  g_PHK);
    cudaGetSymbolAddress((void**)&KV,   g_KV);
    cudaGetSymbolAddress((void**)&KSUM, g_KSUM);
    cudaGetSymbolAddress((void**)&COS,  g_COS);
    cudaGetSymbolAddress((void**)&SIN,  g_SIN);

    dim3 gemmGrid(DD / BN, NTOK / BM);   // (12, 512)

    rope_table_kernel<<<(LL * 32) / 256, 256>>>(COS, SIN);
    embed_kernel<<<(NTOK * DD / 4) / 256, 256>>>(idx, tok_emb, X);

    for (int i = 0; i < NLAYER; i++) {
        const float* Wq_i = Wq + (size_t)i * DD * DD;
        const float* Wk_i = Wk + (size_t)i * DD * DD;
        const float* Wv_i = Wv + (size_t)i * DD * DD;
        const float* Wo_i = Wo + (size_t)i * DD * DD;
        const float* W1_i = W1 + (size_t)i * DD * DD;
        const float* W2_i = W2 + (size_t)i * DD * DD;
        const float* om_i = om + (size_t)i * HDIM * FDIM;

        sgemm_kernel<<<gemmGrid, 256>>>(X, Wq_i, bq + i * DD, nullptr, Q, NTOK, DD, DD, 0);
        sgemm_kernel<<<gemmGrid, 256>>>(X, Wk_i, bk + i * DD, nullptr, K, NTOK, DD, DD, 0);
        sgemm_kernel<<<gemmGrid, 256>>>(X, Wv_i, bv + i * DD, nullptr, V, NTOK, DD, DD, 0);

        rotary_kernel<<<(NTOK * HH * 32) / 256, 256>>>(Q, K, COS, SIN);

        phi_kernel<<<(NTOK * HH) / 256, 256>>>(Q, om_i, nullptr, PHQ);
        phi_kernel<<<(NTOK * HH) / 256, 256>>>(K, om_i, mask,    PHK);

        kv_kernel<<<BB * HH, 256>>>(PHK, V, KV, KSUM);

        attn_out_kernel<<<dim3(LL / 256, BB * HH), 256>>>(PHQ, KV, KSUM, Y);

        // X = Y @ Wo + bo + X (fused residual)
        sgemm_kernel<<<gemmGrid, 256>>>(Y, Wo_i, bo + i * DD, X, X, NTOK, DD, DD, 0);
        // X = LN(X) (in-place)
        ln_kernel<<<NTOK, 256>>>(X, g1 + i * DD, be1 + i * DD, X);
        // Q (reused as FFN hidden) = gelu(X @ W1 + b1)
        sgemm_kernel<<<gemmGrid, 256>>>(X, W1_i, b1 + i * DD, nullptr, Q, NTOK, DD, DD, 1);
        // Y = Q @ W2 + b2 + X (fused residual)
        sgemm_kernel<<<gemmGrid, 256>>>(Q, W2_i, b2 + i * DD, X, Y, NTOK, DD, DD, 0);
        // X = LN(Y)
        ln_kernel<<<NTOK, 256>>>(Y, g2 + i * DD, be2 + i * DD, X);
    }

    // final LayerNorm into output
    ln_kernel<<<NTOK, 256>>>(X, gf, bf, out);
}

// round 2
// speedup vs baseline: 1.9847x; 1.9847x over previous
#include <cuda_runtime.h>
#include <math.h>
#include <stdint.h>

// Problem constants
#define BB      16
#define LL      2048
#define DD      768
#define HH      12
#define NLAYER  4
#define FDIM    32
#define HDIM    64
#define NTOK    (BB * LL)            // 32768
#define ATTN_EPS 1e-6f
#define LN_EPS   1e-5f

// ---------------------------------------------------------------------------
// Scratch buffers (static __device__ — no runtime allocation)
// ---------------------------------------------------------------------------
__device__ float g_X [(size_t)NTOK * DD];   // residual stream
__device__ float g_Y [(size_t)NTOK * DD];   // attn/ffn outputs
__device__ float g_Q [(size_t)NTOK * DD];   // Q projection / FFN hidden (reused)
__device__ float g_K [(size_t)NTOK * DD];
__device__ float g_V [(size_t)NTOK * DD];
__device__ float g_PHQ[(size_t)NTOK * HH * FDIM];
__device__ float g_PHK[(size_t)NTOK * HH * FDIM];
__device__ float g_KV  [BB * HH * FDIM * HDIM];
__device__ float g_KSUM[BB * HH * FDIM];
__device__ float g_COS [LL * (HDIM / 2)];
__device__ float g_SIN [LL * (HDIM / 2)];

// ---------------------------------------------------------------------------
// Embedding gather
// ---------------------------------------------------------------------------
__global__ __launch_bounds__(256) void embed_kernel(
    const int* __restrict__ idx, const float* __restrict__ emb,
    float* __restrict__ X)
{
    int i   = blockIdx.x * 256 + threadIdx.x;
    int tok = i / (DD / 4);
    int c4  = i % (DD / 4);
    const float4* src = (const float4*)(emb + (size_t)idx[tok] * DD);
    ((float4*)X)[i] = src[c4];
}

// ---------------------------------------------------------------------------
// Rotary cos/sin table, double precision trig
// ---------------------------------------------------------------------------
__global__ __launch_bounds__(256) void rope_table_kernel(
    float* __restrict__ cosT, float* __restrict__ sinT)
{
    int i = blockIdx.x * 256 + threadIdx.x;
    int j = i & 31;
    int l = i >> 5;
    double inv = pow(10000.0, -(double)(2 * j) / (double)HDIM);
    double fr  = (double)l * inv;
    cosT[i] = (float)cos(fr);
    sinT[i] = (float)sin(fr);
}

// ---------------------------------------------------------------------------
// Rotary in-place on Q and K
// ---------------------------------------------------------------------------
__global__ __launch_bounds__(256) void rotary_kernel(
    float* __restrict__ Q, float* __restrict__ K,
    const float* __restrict__ cosT, const float* __restrict__ sinT)
{
    int i   = blockIdx.x * 256 + threadIdx.x;
    int j   = i & 31;
    int rem = i >> 5;
    int h   = rem % HH;
    int n   = rem / HH;
    int l   = n & (LL - 1);
    float c = cosT[l * 32 + j];
    float s = sinT[l * 32 + j];
    size_t base = (size_t)n * DD + h * HDIM + j;
    float x1, x2;
    x1 = Q[base]; x2 = Q[base + 32];
    Q[base]      = x1 * c - x2 * s;
    Q[base + 32] = x2 * c + x1 * s;
    x1 = K[base]; x2 = K[base + 32];
    K[base]      = x1 * c - x2 * s;
    K[base + 32] = x2 * c + x1 * s;
}

// ---------------------------------------------------------------------------
// Feature map phi
// ---------------------------------------------------------------------------
__global__ __launch_bounds__(256) void phi_kernel(
    const float* __restrict__ X, const float* __restrict__ omega,
    const int* __restrict__ mask, float* __restrict__ PH)
{
    __shared__ float4 som[HDIM * FDIM / 4];
    int tid = threadIdx.x;
    #pragma unroll
    for (int p = 0; p < 2; p++)
        som[tid + p * 256] = ((const float4*)omega)[tid + p * 256];
    __syncthreads();

    int id = blockIdx.x * 256 + tid;
    int n  = id / HH;
    int h  = id % HH;

    float q[HDIM];
    const float4* src = (const float4*)(X + (size_t)n * DD + h * HDIM);
    #pragma unroll
    for (int i = 0; i < HDIM / 4; i++) {
        float4 v = src[i];
        q[i * 4 + 0] = v.x; q[i * 4 + 1] = v.y;
        q[i * 4 + 2] = v.z; q[i * 4 + 3] = v.w;
    }
    float m = mask ? (float)mask[n] : 1.0f;

    float4* out = (float4*)(PH + (size_t)id * FDIM);
    #pragma unroll
    for (int f4 = 0; f4 < FDIM / 4; f4++) {
        float4 acc = make_float4(0.f, 0.f, 0.f, 0.f);
        #pragma unroll
        for (int d = 0; d < HDIM; d++) {
            float4 w = som[d * 8 + f4];
            acc.x += q[d] * w.x; acc.y += q[d] * w.y;
            acc.z += q[d] * w.z; acc.w += q[d] * w.w;
        }
        acc.x = fmaxf(acc.x, 0.f) * m; acc.y = fmaxf(acc.y, 0.f) * m;
        acc.z = fmaxf(acc.z, 0.f) * m; acc.w = fmaxf(acc.w, 0.f) * m;
        out[f4] = acc;
    }
}

// ---------------------------------------------------------------------------
// KV state reduction
// ---------------------------------------------------------------------------
__global__ __launch_bounds__(256) void kv_kernel(
    const float* __restrict__ PHK, const float* __restrict__ V,
    float* __restrict__ KV, float* __restrict__ KSUM)
{
    __shared__ float sph[32 * FDIM];
    __shared__ float sv [32 * HDIM];
    int bh = blockIdx.x;
    int b  = bh / HH;
    int h  = bh % HH;
    int tid = threadIdx.x;
    int f  = tid & 31;
    int dg = tid >> 5;
    float acc[8] = {0.f,0.f,0.f,0.f,0.f,0.f,0.f,0.f};
    float sacc = 0.f;

    int rA  = tid >> 3, cA = (tid & 7) * 4;
    for (int l0 = 0; l0 < LL; l0 += 32) {
        *(float4*)&sph[rA * FDIM + cA] =
            *(const float4*)(PHK + ((size_t)(b * LL + l0 + rA) * HH + h) * FDIM + cA);
        #pragma unroll
        for (int p = 0; p < 2; p++) {
            int ii = tid + p * 256;
            int rr = ii >> 4, cc = (ii & 15) * 4;
            *(float4*)&sv[rr * HDIM + cc] =
                *(const float4*)(V + (size_t)(b * LL + l0 + rr) * DD + h * HDIM + cc);
        }
        __syncthreads();
        #pragma unroll 8
        for (int r = 0; r < 32; r++) {
            float ph = sph[r * FDIM + f];
            sacc += ph;
            float4 v0 = *(const float4*)&sv[r * HDIM + dg * 8];
            float4 v1 = *(const float4*)&sv[r * HDIM + dg * 8 + 4];
            acc[0] += ph * v0.x; acc[1] += ph * v0.y;
            acc[2] += ph * v0.z; acc[3] += ph * v0.w;
            acc[4] += ph * v1.x; acc[5] += ph * v1.y;
            acc[6] += ph * v1.z; acc[7] += ph * v1.w;
        }
        __syncthreads();
    }
    float* dst = KV + ((size_t)bh * FDIM + f) * HDIM + dg * 8;
    #pragma unroll
    for (int jj = 0; jj < 8; jj++) dst[jj] = acc[jj];
    if (dg == 0) KSUM[bh * FDIM + f] = sacc;
}

// ---------------------------------------------------------------------------
// Attention output
// ---------------------------------------------------------------------------
__global__ __launch_bounds__(256) void attn_out_kernel(
    const float* __restrict__ PHQ, const float* __restrict__ KV,
    const float* __restrict__ KSUM, float* __restrict__ Y)
{
    __shared__ float4 skv[FDIM * HDIM / 4];
    __shared__ float  sks[FDIM];
    int bh  = blockIdx.y;
    int tid = threadIdx.x;
    #pragma unroll
    for (int p = 0; p < 2; p++)
        skv[tid + p * 256] = ((const float4*)(KV + (size_t)bh * FDIM * HDIM))[tid + p * 256];
    if (tid < FDIM) sks[tid] = KSUM[bh * FDIM + tid];
    __syncthreads();

    int b = bh / HH, h = bh % HH;
    size_t n = (size_t)b * LL + blockIdx.x * 256 + tid;

    float ph[FDIM];
    const float4* src = (const float4*)(PHQ + (n * HH + h) * FDIM);
    #pragma unroll
    for (int i = 0; i < FDIM / 4; i++) {
        float4 v = src[i];
        ph[i * 4 + 0] = v.x; ph[i * 4 + 1] = v.y;
        ph[i * 4 + 2] = v.z; ph[i * 4 + 3] = v.w;
    }
    float den = ATTN_EPS;
    #pragma unroll
    for (int fI = 0; fI < FDIM; fI++) den += ph[fI] * sks[fI];
    float z = 1.0f / den;

    float4* outp = (float4*)(Y + n * DD + h * HDIM);
    #pragma unroll
    for (int d4 = 0; d4 < HDIM / 4; d4++) {
        float4 acc = make_float4(0.f, 0.f, 0.f, 0.f);
        #pragma unroll
        for (int fI = 0; fI < FDIM; fI++) {
            float4 kvv = skv[fI * 16 + d4];
            acc.x += ph[fI] * kvv.x; acc.y += ph[fI] * kvv.y;
            acc.z += ph[fI] * kvv.z; acc.w += ph[fI] * kvv.w;
        }
        acc.x *= z; acc.y *= z; acc.z *= z; acc.w *= z;
        outp[d4] = acc;
    }
}

// ---------------------------------------------------------------------------
// TF32 tensor-core GEMM: C[M,N] = act(A[M,K] @ W[K,N] + bias) (+ R)
// Block tile 128x128x16, 8 warps of 64x32, mma.m16n8k8.tf32, double-buffered.
// ---------------------------------------------------------------------------
#define GBM 128
#define GBN 128
#define GBK 16
#define AS_STR 20      // (20*m + k) mod 32 distinct for m<8,k<4 -> conflict-free
#define BS_STR 136     // (8*k + n) mod 32 distinct for k<4,n<8  -> conflict-free

__device__ __forceinline__ unsigned f2tf(float x) {
    unsigned r;
    asm("cvt.rna.tf32.f32 %0, %1;" : "=r"(r) : "f"(x));
    return r;
}

__device__ __forceinline__ void mma_tf32(float* c, const unsigned* a, const unsigned* b) {
    asm volatile(
        "mma.sync.aligned.m16n8k8.row.col.f32.tf32.tf32.f32 "
        "{%0,%1,%2,%3},{%4,%5,%6,%7},{%8,%9},{%0,%1,%2,%3};"
        : "+f"(c[0]), "+f"(c[1]), "+f"(c[2]), "+f"(c[3])
        : "r"(a[0]), "r"(a[1]), "r"(a[2]), "r"(a[3]), "r"(b[0]), "r"(b[1]));
}

__global__ __launch_bounds__(256, 1) void tfgemm_kernel(
    const float* __restrict__ A, const float* __restrict__ W,
    const float* __restrict__ bias, const float* __restrict__ R,
    float* __restrict__ C, int M, int N, int K, int act)
{
    __shared__ float As[2][GBM][AS_STR];
    __shared__ float Bs[2][GBK][BS_STR];

    int tid  = threadIdx.x;
    int lane = tid & 31;
    int warp = tid >> 5;
    int wm = (warp & 1) * 64;      // warp m-offset within block
    int wn = (warp >> 1) * 32;     // warp n-offset within block
    size_t row0 = (size_t)blockIdx.y * GBM;
    size_t col0 = (size_t)blockIdx.x * GBN;

    float cacc[4][4][4];
    #pragma unroll
    for (int i = 0; i < 4; i++)
        #pragma unroll
        for (int j = 0; j < 4; j++)
            #pragma unroll
            for (int k = 0; k < 4; k++) cacc[i][j][k] = 0.f;

    int am  = tid >> 2;            // A load: row within tile (0..63, +64)
    int ak4 = (tid & 3) << 2;      // A load: k offset (0,4,8,12)
    int br  = tid >> 5;            // B load: k-row (0..7, +8)
    int bc4 = (tid & 31) << 2;     // B load: col (0..124)

    // initial tile (k0 = 0)
    {
        #pragma unroll
        for (int i = 0; i < 2; i++) {
            float4 v = *(const float4*)(A + (row0 + am + i * 64) * K + ak4);
            float4 t;
            t.x = __uint_as_float(f2tf(v.x)); t.y = __uint_as_float(f2tf(v.y));
            t.z = __uint_as_float(f2tf(v.z)); t.w = __uint_as_float(f2tf(v.w));
            *(float4*)&As[0][am + i * 64][ak4] = t;
        }
        #pragma unroll
        for (int i = 0; i < 2; i++) {
            float4 v = *(const float4*)(W + (size_t)(br + i * 8) * N + col0 + bc4);
            float4 t;
            t.x = __uint_as_float(f2tf(v.x)); t.y = __uint_as_float(f2tf(v.y));
            t.z = __uint_as_float(f2tf(v.z)); t.w = __uint_as_float(f2tf(v.w));
            *(float4*)&Bs[0][br + i * 8][bc4] = t;
        }
    }
    __syncthreads();

    int nk = K / GBK;
    for (int t = 0; t < nk; t++) {
        int buf = t & 1;
        float4 pa[2], pb[2];
        bool pre = (t + 1) < nk;
        if (pre) {
            int k0 = (t + 1) * GBK;
            pa[0] = *(const float4*)(A + (row0 + am) * K + k0 + ak4);
            pa[1] = *(const float4*)(A + (row0 + am + 64) * K + k0 + ak4);
            pb[0] = *(const float4*)(W + (size_t)(k0 + br) * N + col0 + bc4);
            pb[1] = *(const float4*)(W + (size_t)(k0 + br + 8) * N + col0 + bc4);
        }

        #pragma unroll
        for (int ks = 0; ks < GBK; ks += 8) {
            unsigned a[4][4], b[4][2];
            int kc = ks + (lane & 3);
            #pragma unroll
            for (int fm = 0; fm < 4; fm++) {
                int r = wm + fm * 16 + (lane >> 2);
                a[fm][0] = __float_as_uint(As[buf][r][kc]);
                a[fm][1] = __float_as_uint(As[buf][r + 8][kc]);
                a[fm][2] = __float_as_uint(As[buf][r][kc + 4]);
                a[fm][3] = __float_as_uint(As[buf][r + 8][kc + 4]);
            }
            #pragma unroll
            for (int fn = 0; fn < 4; fn++) {
                int cn = wn + fn * 8 + (lane >> 2);
                b[fn][0] = __float_as_uint(Bs[buf][kc][cn]);
                b[fn][1] = __float_as_uint(Bs[buf][kc + 4][cn]);
            }
            #pragma unroll
            for (int fm = 0; fm < 4; fm++)
                #pragma unroll
                for (int fn = 0; fn < 4; fn++)
                    mma_tf32(cacc[fm][fn], a[fm], b[fn]);
        }

        if (pre) {
            int nb = buf ^ 1;
            #pragma unroll
            for (int i = 0; i < 2; i++) {
                float4 t;
                t.x = __uint_as_float(f2tf(pa[i].x)); t.y = __uint_as_float(f2tf(pa[i].y));
                t.z = __uint_as_float(f2tf(pa[i].z)); t.w = __uint_as_float(f2tf(pa[i].w));
                *(float4*)&As[nb][am + i * 64][ak4] = t;
            }
            #pragma unroll
            for (int i = 0; i < 2; i++) {
                float4 t;
                t.x = __uint_as_float(f2tf(pb[i].x)); t.y = __uint_as_float(f2tf(pb[i].y));
                t.z = __uint_as_float(f2tf(pb[i].z)); t.w = __uint_as_float(f2tf(pb[i].w));
                *(float4*)&Bs[nb][br + i * 8][bc4] = t;
            }
            __syncthreads();
        }
    }

    // epilogue: bias (+gelu) (+residual)
    #pragma unroll
    for (int fm = 0; fm < 4; fm++) {
        size_t r0 = row0 + wm + fm * 16 + (lane >> 2);
        size_t r1 = r0 + 8;
        #pragma unroll
        for (int fn = 0; fn < 4; fn++) {
            size_t cn = col0 + wn + fn * 8 + 2 * (lane & 3);
            float bx = bias[cn], by = bias[cn + 1];
            float v0 = cacc[fm][fn][0] + bx;
            float v1 = cacc[fm][fn][1] + by;
            float v2 = cacc[fm][fn][2] + bx;
            float v3 = cacc[fm][fn][3] + by;
            if (act == 1) {
                v0 = 0.5f * v0 * (1.f + erff(v0 * 0.70710678118654752f));
                v1 = 0.5f * v1 * (1.f + erff(v1 * 0.70710678118654752f));
                v2 = 0.5f * v2 * (1.f + erff(v2 * 0.70710678118654752f));
                v3 = 0.5f * v3 * (1.f + erff(v3 * 0.70710678118654752f));
            }
            if (R) {
                float2 ra = *(const float2*)(R + r0 * N + cn);
                float2 rb = *(const float2*)(R + r1 * N + cn);
                v0 += ra.x; v1 += ra.y; v2 += rb.x; v3 += rb.y;
            }
            *(float2*)(C + r0 * N + cn) = make_float2(v0, v1);
            *(float2*)(C + r1 * N + cn) = make_float2(v2, v3);
        }
    }
}

// ---------------------------------------------------------------------------
// LayerNorm
// ---------------------------------------------------------------------------
__global__ __launch_bounds__(256) void ln_kernel(
    const float* __restrict__ in, const float* __restrict__ g,
    const float* __restrict__ b, float* __restrict__ out)
{
    __shared__ float sx[DD];
    __shared__ float red[256];
    size_t row = blockIdx.x;
    int tid = threadIdx.x;
    const float* ip = in + row * DD;

    float s = 0.f;
    #pragma unroll
    for (int j = tid; j < DD; j += 256) { float v = ip[j]; sx[j] = v; s += v; }
    red[tid] = s; __syncthreads();
    #pragma unroll
    for (int off = 128; off > 0; off >>= 1) {
        if (tid < off) red[tid] += red[tid + off];
        __syncthreads();
    }
    float mu = red[0] * (1.0f / DD);
    __syncthreads();

    float s2 = 0.f;
    #pragma unroll
    for (int j = tid; j < DD; j += 256) { float d = sx[j] - mu; s2 += d * d; }
    red[tid] = s2; __syncthreads();
    #pragma unroll
    for (int off = 128; off > 0; off >>= 1) {
        if (tid < off) red[tid] += red[tid + off];
        __syncthreads();
    }
    float rstd = rsqrtf(red[0] * (1.0f / DD) + LN_EPS);

    #pragma unroll
    for (int j = tid; j < DD; j += 256)
        out[row * DD + j] = (sx[j] - mu) * rstd * g[j] + b[j];
}

// ---------------------------------------------------------------------------
// Host orchestration
// ---------------------------------------------------------------------------
extern "C" void kernel_launch(void* const* d_in, const int* in_sizes, int n_in,
                              void* d_out, int out_size)
{
    const int*   idx     = (const int*)  d_in[0];
    const int*   mask    = (const int*)  d_in[1];
    const float* tok_emb = (const float*)d_in[2];
    const float* Wq = (const float*)d_in[3];
    const float* bq = (const float*)d_in[4];
    const float* Wk = (const float*)d_in[5];
    const float* bk = (const float*)d_in[6];
    const float* Wv = (const float*)d_in[7];
    const float* bv = (const float*)d_in[8];
    const float* Wo = (const float*)d_in[9];
    const float* bo = (const float*)d_in[10];
    const float* om = (const float*)d_in[11];
    const float* W1 = (const float*)d_in[12];
    const float* b1 = (const float*)d_in[13];
    const float* W2 = (const float*)d_in[14];
    const float* b2 = (const float*)d_in[15];
    const float* g1 = (const float*)d_in[16];
    const float* be1= (const float*)d_in[17];
    const float* g2 = (const float*)d_in[18];
    const float* be2= (const float*)d_in[19];
    const float* gf = (const float*)d_in[20];
    const float* bf = (const float*)d_in[21];
    float* out = (float*)d_out;

    float *X, *Y, *Q, *K, *V, *PHQ, *PHK, *KV, *KSUM, *COS, *SIN;
    cudaGetSymbolAddress((void**)&X,    g_X);
    cudaGetSymbolAddress((void**)&Y,    g_Y);
    cudaGetSymbolAddress((void**)&Q,    g_Q);
    cudaGetSymbolAddress((void**)&K,    g_K);
    cudaGetSymbolAddress((void**)&V,    g_V);
    cudaGetSymbolAddress((void**)&PHQ,  g_PHQ);
    cudaGetSymbolAddress((void**)&PHK,  g_PHK);
    cudaGetSymbolAddress((void**)&KV,   g_KV);
    cudaGetSymbolAddress((void**)&KSUM, g_KSUM);
    cudaGetSymbolAddress((void**)&COS,  g_COS);
    cudaGetSymbolAddress((void**)&SIN,  g_SIN);

    dim3 gemmGrid(DD / GBN, NTOK / GBM);   // (6, 256)

    rope_table_kernel<<<(LL * 32) / 256, 256>>>(COS, SIN);
    embed_kernel<<<(NTOK * DD / 4) / 256, 256>>>(idx, tok_emb, X);

    for (int i = 0; i < NLAYER; i++) {
        const float* Wq_i = Wq + (size_t)i * DD * DD;
        const float* Wk_i = Wk + (size_t)i * DD * DD;
        const float* Wv_i = Wv + (size_t)i * DD * DD;
        const float* Wo_i = Wo + (size_t)i * DD * DD;
        const float* W1_i = W1 + (size_t)i * DD * DD;
        const float* W2_i = W2 + (size_t)i * DD * DD;
        const float* om_i = om + (size_t)i * HDIM * FDIM;

        tfgemm_kernel<<<gemmGrid, 256>>>(X, Wq_i, bq + i * DD, nullptr, Q, NTOK, DD, DD, 0);
        tfgemm_kernel<<<gemmGrid, 256>>>(X, Wk_i, bk + i * DD, nullptr, K, NTOK, DD, DD, 0);
        tfgemm_kernel<<<gemmGrid, 256>>>(X, Wv_i, bv + i * DD, nullptr, V, NTOK, DD, DD, 0);

        rotary_kernel<<<(NTOK * HH * 32) / 256, 256>>>(Q, K, COS, SIN);

        phi_kernel<<<(NTOK * HH) / 256, 256>>>(Q, om_i, nullptr, PHQ);
        phi_kernel<<<(NTOK * HH) / 256, 256>>>(K, om_i, mask,    PHK);

        kv_kernel<<<BB * HH, 256>>>(PHK, V, KV, KSUM);

        attn_out_kernel<<<dim3(LL / 256, BB * HH), 256>>>(PHQ, KV, KSUM, Y);

        // X = Y @ Wo + bo + X (fused residual)
        tfgemm_kernel<<<gemmGrid, 256>>>(Y, Wo_i, bo + i * DD, X, X, NTOK, DD, DD, 0);
        // X = LN(X) (in-place)
        ln_kernel<<<NTOK, 256>>>(X, g1 + i * DD, be1 + i * DD, X);
        // Q (reused as FFN hidden) = gelu(X @ W1 + b1)
        tfgemm_kernel<<<gemmGrid, 256>>>(X, W1_i, b1 + i * DD, nullptr, Q, NTOK, DD, DD, 1);
        // Y = Q @ W2 + b2 + X (fused residual)
        tfgemm_kernel<<<gemmGrid, 256>>>(Q, W2_i, b2 + i * DD, X, Y, NTOK, DD, DD, 0);
        // X = LN(Y)
        ln_kernel<<<NTOK, 256>>>(Y, g2 + i * DD, be2 + i * DD, X);
    }

    ln_kernel<<<NTOK, 256>>>(X, gf, bf, out);
}

// round 4
// speedup vs baseline: 3.1759x; 1.6002x over previous
#include <cuda_runtime.h>
#include <math.h>
#include <stdint.h>

// Problem constants
#define BB      16
#define LL      2048
#define DD      768
#define HH      12
#define NLAYER  4
#define FDIM    32
#define HDIM    64
#define NTOK    (BB * LL)            // 32768
#define ATTN_EPS 1e-6f
#define LN_EPS   1e-5f

// ---------------------------------------------------------------------------
// Scratch buffers
// ---------------------------------------------------------------------------
__device__ float g_X [(size_t)NTOK * DD];
__device__ float g_Y [(size_t)NTOK * DD];
__device__ float g_Q [(size_t)NTOK * DD];
__device__ float g_K [(size_t)NTOK * DD];
__device__ float g_V [(size_t)NTOK * DD];
__device__ float g_PHQ[(size_t)NTOK * HH * FDIM];
__device__ float g_PHK[(size_t)NTOK * HH * FDIM];
__device__ float g_KV  [BB * HH * FDIM * HDIM];
__device__ float g_KSUM[BB * HH * FDIM];
__device__ float g_COS [LL * (HDIM / 2)];
__device__ float g_SIN [LL * (HDIM / 2)];

// ---------------------------------------------------------------------------
// PTX helpers
// ---------------------------------------------------------------------------
__device__ __forceinline__ void cpa16(uint32_t d, const void* s) {
    asm volatile("cp.async.cg.shared.global [%0], [%1], 16;" :: "r"(d), "l"(s));
}
#define CPA_COMMIT() asm volatile("cp.async.commit_group;" ::: "memory")
#define CPA_WAIT1()  asm volatile("cp.async.wait_group 1;" ::: "memory")

__device__ __forceinline__ uint32_t smem_u32(const void* p) {
    uint32_t a;
    asm("{ .reg .u64 t; cvta.to.shared.u64 t, %1; cvt.u32.u64 %0, t; }"
        : "=r"(a) : "l"(p));
    return a;
}

__device__ __forceinline__ void mma_tf32(float* c, const unsigned* a, const unsigned* b) {
    asm volatile(
        "mma.sync.aligned.m16n8k8.row.col.f32.tf32.tf32.f32 "
        "{%0,%1,%2,%3},{%4,%5,%6,%7},{%8,%9},{%0,%1,%2,%3};"
        : "+f"(c[0]), "+f"(c[1]), "+f"(c[2]), "+f"(c[3])
        : "r"(a[0]), "r"(a[1]), "r"(a[2]), "r"(a[3]), "r"(b[0]), "r"(b[1]));
}

// ---------------------------------------------------------------------------
// Pipelined tf32 GEMM: C[32768,768] = act(A @ W + bias) (+R)
// 128x128x32 tile, 8 warps of 64x32, cp.async 3-stage (lookahead 2).
// A smem: [128][36] floats (row-major, pad->conflict-free fragment reads)
// B smem: [32][136] floats (row-major from W[K][N], conflict-free)
// ---------------------------------------------------------------------------
#define TM 128
#define TN 128
#define TBK 32
#define NST 3
#define A_STR 36
#define B_STR 136
#define A_TILE_B (TM * A_STR * 4)           // 18432
#define B_TILE_B (TBK * B_STR * 4)          // 17408
#define STAGE_B  (A_TILE_B + B_TILE_B)      // 35840
#define OFF_BIAS (NST * STAGE_B)            // 107520
#define SMEM_GEMM (OFF_BIAS + TN * 4)       // 108032
#define NKT (DD / TBK)                      // 24

__global__ __launch_bounds__(256, 2) void pgemm_kernel(
    const float* __restrict__ A, const float* __restrict__ W,
    const float* __restrict__ bias, const float* __restrict__ R,
    float* __restrict__ C, int act)
{
    extern __shared__ char smem[];
    uint32_t sb = smem_u32(smem);
    int tid = threadIdx.x, lane = tid & 31, warp = tid >> 5;
    int wm = (warp & 1) * 64;
    int wn = (warp >> 1) * 32;
    size_t row0 = (size_t)blockIdx.y * TM;
    size_t col0 = (size_t)blockIdx.x * TN;

    if (tid < TN) *(float*)(smem + OFF_BIAS + tid * 4) = bias[col0 + tid];

    // stage loader: K-slice u -> buffer u%3   (8 cp.async per thread)
    int ar = tid >> 3, akc = tid & 7;            // A: 4 chunk sets
    int bk = tid >> 5, bnc = tid & 31;           // B: 4 chunk sets
    auto load_stage = [&](int u) {
        uint32_t st = sb + (u % NST) * STAGE_B;
        int k0 = u * TBK;
        #pragma unroll
        for (int i = 0; i < 4; i++) {
            int r = ar + i * 32;
            cpa16(st + r * (A_STR * 4) + akc * 16,
                  A + (row0 + r) * DD + k0 + akc * 4);
        }
        uint32_t bbase = st + A_TILE_B;
        #pragma unroll
        for (int i = 0; i < 4; i++) {
            int k = bk + i * 8;
            cpa16(bbase + k * (B_STR * 4) + bnc * 16,
                  W + (size_t)(k0 + k) * DD + col0 + bnc * 4);
        }
    };

    float acc[4][4][4];
    #pragma unroll
    for (int i = 0; i < 4; i++)
        #pragma unroll
        for (int j = 0; j < 4; j++)
            #pragma unroll
            for (int k = 0; k < 4; k++) acc[i][j][k] = 0.f;

    load_stage(0); CPA_COMMIT();
    load_stage(1); CPA_COMMIT();

    for (int t = 0; t < NKT; t++) {
        CPA_WAIT1();            // stage t arrived (per-thread groups)
        __syncthreads();        // cross-thread visibility + buffer reuse guard
        if (t + 2 < NKT) load_stage(t + 2);
        CPA_COMMIT();           // commit (possibly empty) to keep group count
        const float* sA = (const float*)(smem + (t % NST) * STAGE_B);
        const float* sB = (const float*)(smem + (t % NST) * STAGE_B + A_TILE_B);
        #pragma unroll
        for (int ks = 0; ks < 4; ks++) {
            int kc = ks * 8 + (lane & 3);
            unsigned a[4][4], b[4][2];
            #pragma unroll
            for (int fm = 0; fm < 4; fm++) {
                int r = wm + fm * 16 + (lane >> 2);
                a[fm][0] = __float_as_uint(sA[r * A_STR + kc]);
                a[fm][1] = __float_as_uint(sA[(r + 8) * A_STR + kc]);
                a[fm][2] = __float_as_uint(sA[r * A_STR + kc + 4]);
                a[fm][3] = __float_as_uint(sA[(r + 8) * A_STR + kc + 4]);
            }
            #pragma unroll
            for (int fn = 0; fn < 4; fn++) {
                int cn = wn + fn * 8 + (lane >> 2);
                b[fn][0] = __float_as_uint(sB[kc * B_STR + cn]);
                b[fn][1] = __float_as_uint(sB[(kc + 4) * B_STR + cn]);
            }
            #pragma unroll
            for (int fm = 0; fm < 4; fm++)
                #pragma unroll
                for (int fn = 0; fn < 4; fn++)
                    mma_tf32(acc[fm][fn], a[fm], b[fn]);
        }
    }

    // epilogue
    const float* sbias = (const float*)(smem + OFF_BIAS);
    #pragma unroll
    for (int fm = 0; fm < 4; fm++) {
        size_t r0 = row0 + wm + fm * 16 + (lane >> 2);
        size_t r1 = r0 + 8;
        #pragma unroll
        for (int fn = 0; fn < 4; fn++) {
            int cl = wn + fn * 8 + 2 * (lane & 3);
            size_t cn = col0 + cl;
            float bx = sbias[cl], by = sbias[cl + 1];
            float v0 = acc[fm][fn][0] + bx;
            float v1 = acc[fm][fn][1] + by;
            float v2 = acc[fm][fn][2] + bx;
            float v3 = acc[fm][fn][3] + by;
            if (act == 1) {
                v0 = 0.5f * v0 * (1.f + erff(v0 * 0.70710678118654752f));
                v1 = 0.5f * v1 * (1.f + erff(v1 * 0.70710678118654752f));
                v2 = 0.5f * v2 * (1.f + erff(v2 * 0.70710678118654752f));
                v3 = 0.5f * v3 * (1.f + erff(v3 * 0.70710678118654752f));
            }
            if (R) {
                float2 ra = *(const float2*)(R + r0 * DD + cn);
                float2 rb = *(const float2*)(R + r1 * DD + cn);
                v0 += ra.x; v1 += ra.y; v2 += rb.x; v3 += rb.y;
            }
            *(float2*)(C + r0 * DD + cn) = make_float2(v0, v1);
            *(float2*)(C + r1 * DD + cn) = make_float2(v2, v3);
        }
    }
}

// ---------------------------------------------------------------------------
// Embedding gather
// ---------------------------------------------------------------------------
__global__ __launch_bounds__(256) void embed_kernel(
    const int* __restrict__ idx, const float* __restrict__ emb,
    float* __restrict__ X)
{
    int i   = blockIdx.x * 256 + threadIdx.x;
    int tok = i / (DD / 4);
    int c4  = i % (DD / 4);
    const float4* src = (const float4*)(emb + (size_t)idx[tok] * DD);
    ((float4*)X)[i] = src[c4];
}

// ---------------------------------------------------------------------------
// Rotary cos/sin table, double precision trig
// ---------------------------------------------------------------------------
__global__ __launch_bounds__(256) void rope_table_kernel(
    float* __restrict__ cosT, float* __restrict__ sinT)
{
    int i = blockIdx.x * 256 + threadIdx.x;
    int j = i & 31;
    int l = i >> 5;
    double inv = pow(10000.0, -(double)(2 * j) / (double)HDIM);
    double fr  = (double)l * inv;
    cosT[i] = (float)cos(fr);
    sinT[i] = (float)sin(fr);
}

// ---------------------------------------------------------------------------
// Fused rotary + feature map:
// PH[n,h,f] = relu( sum_d rot(X[n,h,:])[d] * omega[d,f] ) * mask?
// ---------------------------------------------------------------------------
__global__ __launch_bounds__(256) void phi_rot_kernel(
    const float* __restrict__ X, const float* __restrict__ omega,
    const float* __restrict__ cosT, const float* __restrict__ sinT,
    const int* __restrict__ mask, float* __restrict__ PH)
{
    __shared__ float4 som[HDIM * FDIM / 4];
    int tid = threadIdx.x;
    #pragma unroll
    for (int p = 0; p < 2; p++)
        som[tid + p * 256] = ((const float4*)omega)[tid + p * 256];
    __syncthreads();

    int id = blockIdx.x * 256 + tid;
    int n  = id / HH;
    int h  = id % HH;
    int l  = n & (LL - 1);

    float q[HDIM];
    const float4* src = (const float4*)(X + (size_t)n * DD + h * HDIM);
    #pragma unroll
    for (int i = 0; i < HDIM / 4; i++) {
        float4 v = src[i];
        q[i * 4 + 0] = v.x; q[i * 4 + 1] = v.y;
        q[i * 4 + 2] = v.z; q[i * 4 + 3] = v.w;
    }
    // rotary in registers
    #pragma unroll
    for (int j = 0; j < 32; j++) {
        float c = cosT[l * 32 + j];
        float s = sinT[l * 32 + j];
        float x1 = q[j], x2 = q[j + 32];
        q[j]      = x1 * c - x2 * s;
        q[j + 32] = x2 * c + x1 * s;
    }
    float m = mask ? (float)mask[n] : 1.0f;

    float4* out = (float4*)(PH + (size_t)id * FDIM);
    #pragma unroll
    for (int f4 = 0; f4 < FDIM / 4; f4++) {
        float4 acc = make_float4(0.f, 0.f, 0.f, 0.f);
        #pragma unroll
        for (int d = 0; d < HDIM; d++) {
            float4 w = som[d * 8 + f4];
            acc.x += q[d] * w.x; acc.y += q[d] * w.y;
            acc.z += q[d] * w.z; acc.w += q[d] * w.w;
        }
        acc.x = fmaxf(acc.x, 0.f) * m; acc.y = fmaxf(acc.y, 0.f) * m;
        acc.z = fmaxf(acc.z, 0.f) * m; acc.w = fmaxf(acc.w, 0.f) * m;
        out[f4] = acc;
    }
}

// ---------------------------------------------------------------------------
// KV state reduction
// ---------------------------------------------------------------------------
__global__ __launch_bounds__(256) void kv_kernel(
    const float* __restrict__ PHK, const float* __restrict__ V,
    float* __restrict__ KV, float* __restrict__ KSUM)
{
    __shared__ float sph[32 * FDIM];
    __shared__ float sv [32 * HDIM];
    int bh = blockIdx.x;
    int b  = bh / HH;
    int h  = bh % HH;
    int tid = threadIdx.x;
    int f  = tid & 31;
    int dg = tid >> 5;
    float acc[8] = {0.f,0.f,0.f,0.f,0.f,0.f,0.f,0.f};
    float sacc = 0.f;

    int rA  = tid >> 3, cA = (tid & 7) * 4;
    for (int l0 = 0; l0 < LL; l0 += 32) {
        *(float4*)&sph[rA * FDIM + cA] =
            *(const float4*)(PHK + ((size_t)(b * LL + l0 + rA) * HH + h) * FDIM + cA);
        #pragma unroll
        for (int p = 0; p < 2; p++) {
            int ii = tid + p * 256;
            int rr = ii >> 4, cc = (ii & 15) * 4;
            *(float4*)&sv[rr * HDIM + cc] =
                *(const float4*)(V + (size_t)(b * LL + l0 + rr) * DD + h * HDIM + cc);
        }
        __syncthreads();
        #pragma unroll 8
        for (int r = 0; r < 32; r++) {
            float ph = sph[r * FDIM + f];
            sacc += ph;
            float4 v0 = *(const float4*)&sv[r * HDIM + dg * 8];
            float4 v1 = *(const float4*)&sv[r * HDIM + dg * 8 + 4];
            acc[0] += ph * v0.x; acc[1] += ph * v0.y;
            acc[2] += ph * v0.z; acc[3] += ph * v0.w;
            acc[4] += ph * v1.x; acc[5] += ph * v1.y;
            acc[6] += ph * v1.z; acc[7] += ph * v1.w;
        }
        __syncthreads();
    }
    float* dst = KV + ((size_t)bh * FDIM + f) * HDIM + dg * 8;
    #pragma unroll
    for (int jj = 0; jj < 8; jj++) dst[jj] = acc[jj];
    if (dg == 0) KSUM[bh * FDIM + f] = sacc;
}

// ---------------------------------------------------------------------------
// Attention output
// ---------------------------------------------------------------------------
__global__ __launch_bounds__(256) void attn_out_kernel(
    const float* __restrict__ PHQ, const float* __restrict__ KV,
    const float* __restrict__ KSUM, float* __restrict__ Y)
{
    __shared__ float4 skv[FDIM * HDIM / 4];
    __shared__ float  sks[FDIM];
    int bh  = blockIdx.y;
    int tid = threadIdx.x;
    #pragma unroll
    for (int p = 0; p < 2; p++)
        skv[tid + p * 256] = ((const float4*)(KV + (size_t)bh * FDIM * HDIM))[tid + p * 256];
    if (tid < FDIM) sks[tid] = KSUM[bh * FDIM + tid];
    __syncthreads();

    int b = bh / HH, h = bh % HH;
    size_t n = (size_t)b * LL + blockIdx.x * 256 + tid;

    float ph[FDIM];
    const float4* src = (const float4*)(PHQ + (n * HH + h) * FDIM);
    #pragma unroll
    for (int i = 0; i < FDIM / 4; i++) {
        float4 v = src[i];
        ph[i * 4 + 0] = v.x; ph[i * 4 + 1] = v.y;
        ph[i * 4 + 2] = v.z; ph[i * 4 + 3] = v.w;
    }
    float den = ATTN_EPS;
    #pragma unroll
    for (int fI = 0; fI < FDIM; fI++) den += ph[fI] * sks[fI];
    float z = 1.0f / den;

    float4* outp = (float4*)(Y + n * DD + h * HDIM);
    #pragma unroll
    for (int d4 = 0; d4 < HDIM / 4; d4++) {
        float4 acc = make_float4(0.f, 0.f, 0.f, 0.f);
        #pragma unroll
        for (int fI = 0; fI < FDIM; fI++) {
            float4 kvv = skv[fI * 16 + d4];
            acc.x += ph[fI] * kvv.x; acc.y += ph[fI] * kvv.y;
            acc.z += ph[fI] * kvv.z; acc.w += ph[fI] * kvv.w;
        }
        acc.x *= z; acc.y *= z; acc.z *= z; acc.w *= z;
        outp[d4] = acc;
    }
}

// ---------------------------------------------------------------------------
// LayerNorm
// ---------------------------------------------------------------------------
__global__ __launch_bounds__(256) void ln_kernel(
    const float* __restrict__ in, const float* __restrict__ g,
    const float* __restrict__ b, float* __restrict__ out)
{
    __shared__ float sx[DD];
    __shared__ float red[256];
    size_t row = blockIdx.x;
    int tid = threadIdx.x;
    const float* ip = in + row * DD;

    float s = 0.f;
    #pragma unroll
    for (int j = tid; j < DD; j += 256) { float v = ip[j]; sx[j] = v; s += v; }
    red[tid] = s; __syncthreads();
    #pragma unroll
    for (int off = 128; off > 0; off >>= 1) {
        if (tid < off) red[tid] += red[tid + off];
        __syncthreads();
    }
    float mu = red[0] * (1.0f / DD);
    __syncthreads();

    float s2 = 0.f;
    #pragma unroll
    for (int j = tid; j < DD; j += 256) { float d = sx[j] - mu; s2 += d * d; }
    red[tid] = s2; __syncthreads();
    #pragma unroll
    for (int off = 128; off > 0; off >>= 1) {
        if (tid < off) red[tid] += red[tid + off];
        __syncthreads();
    }
    float rstd = rsqrtf(red[0] * (1.0f / DD) + LN_EPS);

    #pragma unroll
    for (int j = tid; j < DD; j += 256)
        out[row * DD + j] = (sx[j] - mu) * rstd * g[j] + b[j];
}

// ---------------------------------------------------------------------------
// Host orchestration
// ---------------------------------------------------------------------------
extern "C" void kernel_launch(void* const* d_in, const int* in_sizes, int n_in,
                              void* d_out, int out_size)
{
    const int*   idx     = (const int*)  d_in[0];
    const int*   mask    = (const int*)  d_in[1];
    const float* tok_emb = (const float*)d_in[2];
    const float* Wq = (const float*)d_in[3];
    const float* bq = (const float*)d_in[4];
    const float* Wk = (const float*)d_in[5];
    const float* bk = (const float*)d_in[6];
    const float* Wv = (const float*)d_in[7];
    const float* bv = (const float*)d_in[8];
    const float* Wo = (const float*)d_in[9];
    const float* bo = (const float*)d_in[10];
    const float* om = (const float*)d_in[11];
    const float* W1 = (const float*)d_in[12];
    const float* b1 = (const float*)d_in[13];
    const float* W2 = (const float*)d_in[14];
    const float* b2 = (const float*)d_in[15];
    const float* g1 = (const float*)d_in[16];
    const float* be1= (const float*)d_in[17];
    const float* g2 = (const float*)d_in[18];
    const float* be2= (const float*)d_in[19];
    const float* gf = (const float*)d_in[20];
    const float* bf = (const float*)d_in[21];
    float* out = (float*)d_out;

    float *X, *Y, *Q, *K, *V, *PHQ, *PHK, *KV, *KSUM, *COS, *SIN;
    cudaGetSymbolAddress((void**)&X,    g_X);
    cudaGetSymbolAddress((void**)&Y,    g_Y);
    cudaGetSymbolAddress((void**)&Q,    g_Q);
    cudaGetSymbolAddress((void**)&K,    g_K);
    cudaGetSymbolAddress((void**)&V,    g_V);
    cudaGetSymbolAddress((void**)&PHQ,  g_PHQ);
    cudaGetSymbolAddress((void**)&PHK,  g_PHK);
    cudaGetSymbolAddress((void**)&KV,   g_KV);
    cudaGetSymbolAddress((void**)&KSUM, g_KSUM);
    cudaGetSymbolAddress((void**)&COS,  g_COS);
    cudaGetSymbolAddress((void**)&SIN,  g_SIN);

    cudaFuncSetAttribute(pgemm_kernel,
                         cudaFuncAttributeMaxDynamicSharedMemorySize, SMEM_GEMM);

    const size_t WMAT = (size_t)DD * DD;
    dim3 gGrid(DD / TN, NTOK / TM);   // (6, 256)

    rope_table_kernel<<<(LL * 32) / 256, 256>>>(COS, SIN);
    embed_kernel<<<(NTOK * DD / 4) / 256, 256>>>(idx, tok_emb, X);

    for (int i = 0; i < NLAYER; i++) {
        const float* om_i = om + (size_t)i * HDIM * FDIM;

        pgemm_kernel<<<gGrid, 256, SMEM_GEMM>>>(X, Wq + i * WMAT, bq + i * DD, nullptr, Q, 0);
        pgemm_kernel<<<gGrid, 256, SMEM_GEMM>>>(X, Wk + i * WMAT, bk + i * DD, nullptr, K, 0);
        pgemm_kernel<<<gGrid, 256, SMEM_GEMM>>>(X, Wv + i * WMAT, bv + i * DD, nullptr, V, 0);

        phi_rot_kernel<<<(NTOK * HH) / 256, 256>>>(Q, om_i, COS, SIN, nullptr, PHQ);
        phi_rot_kernel<<<(NTOK * HH) / 256, 256>>>(K, om_i, COS, SIN, mask,    PHK);

        kv_kernel<<<BB * HH, 256>>>(PHK, V, KV, KSUM);

        attn_out_kernel<<<dim3(LL / 256, BB * HH), 256>>>(PHQ, KV, KSUM, Y);

        // X = Y @ Wo + bo + X
        pgemm_kernel<<<gGrid, 256, SMEM_GEMM>>>(Y, Wo + i * WMAT, bo + i * DD, X, X, 0);
        ln_kernel<<<NTOK, 256>>>(X, g1 + i * DD, be1 + i * DD, X);
        // Q = gelu(X @ W1 + b1)
        pgemm_kernel<<<gGrid, 256, SMEM_GEMM>>>(X, W1 + i * WMAT, b1 + i * DD, nullptr, Q, 1);
        // Y = Q @ W2 + b2 + X
        pgemm_kernel<<<gGrid, 256, SMEM_GEMM>>>(Q, W2 + i * WMAT, b2 + i * DD, X, Y, 0);
        ln_kernel<<<NTOK, 256>>>(Y, g2 + i * DD, be2 + i * DD, X);
    }

    ln_kernel<<<NTOK, 256>>>(X, gf, bf, out);
}

// round 8
// speedup vs baseline: 3.4106x; 1.0739x over previous
#include <cuda_runtime.h>
#include <math.h>
#include <stdint.h>

// Problem constants
#define BB      16
#define LL      2048
#define DD      768
#define HH      12
#define NLAYER  4
#define FDIM    32
#define HDIM    64
#define NTOK    (BB * LL)            // 32768
#define ATTN_EPS 1e-6f
#define LN_EPS   1e-5f
#define NBH     (BB * HH)            // 192
#define KVCH    4                    // kv L-split chunks

// ---------------------------------------------------------------------------
// Scratch buffers
// ---------------------------------------------------------------------------
__device__ float g_X [(size_t)NTOK * DD];
__device__ float g_Y [(size_t)NTOK * DD];
__device__ float g_Q [(size_t)NTOK * DD];
__device__ float g_K [(size_t)NTOK * DD];
__device__ float g_V [(size_t)NTOK * DD];
__device__ float g_PHQ[(size_t)NTOK * HH * FDIM];
__device__ float g_PHK[(size_t)NTOK * HH * FDIM];
__device__ float g_KV  [NBH * FDIM * HDIM];
__device__ float g_KSUM[NBH * FDIM];
__device__ float g_KVP [KVCH * NBH * FDIM * HDIM];
__device__ float g_KSP [KVCH * NBH * FDIM];
__device__ float g_COS [LL * (HDIM / 2)];
__device__ float g_SIN [LL * (HDIM / 2)];

// ---------------------------------------------------------------------------
// PTX helpers
// ---------------------------------------------------------------------------
__device__ __forceinline__ void cpa16(uint32_t d, const void* s) {
    asm volatile("cp.async.cg.shared.global [%0], [%1], 16;" :: "r"(d), "l"(s));
}
#define CPA_COMMIT() asm volatile("cp.async.commit_group;" ::: "memory")
#define CPA_WAIT1()  asm volatile("cp.async.wait_group 1;" ::: "memory")

__device__ __forceinline__ uint32_t smem_u32(const void* p) {
    uint32_t a;
    asm("{ .reg .u64 t; cvta.to.shared.u64 t, %1; cvt.u32.u64 %0, t; }"
        : "=r"(a) : "l"(p));
    return a;
}

__device__ __forceinline__ void mma_tf32(float* c, const unsigned* a, const unsigned* b) {
    asm volatile(
        "mma.sync.aligned.m16n8k8.row.col.f32.tf32.tf32.f32 "
        "{%0,%1,%2,%3},{%4,%5,%6,%7},{%8,%9},{%0,%1,%2,%3};"
        : "+f"(c[0]), "+f"(c[1]), "+f"(c[2]), "+f"(c[3])
        : "r"(a[0]), "r"(a[1]), "r"(a[2]), "r"(a[3]), "r"(b[0]), "r"(b[1]));
}

// ---------------------------------------------------------------------------
// Pipelined tf32 GEMM (R4-proven, verbatim): C = act(A @ W + bias) (+R)
// 128x128x32 tile, 8 warps of 64x32, cp.async 3-stage (lookahead 2).
// ---------------------------------------------------------------------------
#define TM 128
#define TN 128
#define TBK 32
#define NST 3
#define A_STR 36
#define B_STR 136
#define A_TILE_B (TM * A_STR * 4)           // 18432
#define B_TILE_B (TBK * B_STR * 4)          // 17408
#define STAGE_B  (A_TILE_B + B_TILE_B)      // 35840
#define OFF_BIAS (NST * STAGE_B)            // 107520
#define SMEM_GEMM (OFF_BIAS + TN * 4)       // 108032
#define NKT (DD / TBK)                      // 24

__global__ __launch_bounds__(256, 2) void pgemm_kernel(
    const float* __restrict__ A, const float* __restrict__ W,
    const float* __restrict__ bias, const float* __restrict__ R,
    float* __restrict__ C, int act)
{
    extern __shared__ char smem[];
    uint32_t sb = smem_u32(smem);
    int tid = threadIdx.x, lane = tid & 31, warp = tid >> 5;
    int wm = (warp & 1) * 64;
    int wn = (warp >> 1) * 32;
    size_t row0 = (size_t)blockIdx.y * TM;
    size_t col0 = (size_t)blockIdx.x * TN;

    if (tid < TN) *(float*)(smem + OFF_BIAS + tid * 4) = bias[col0 + tid];

    int ar = tid >> 3, akc = tid & 7;            // A: 4 chunk sets
    int bk = tid >> 5, bnc = tid & 31;           // B: 4 chunk sets
    auto load_stage = [&](int u) {
        uint32_t st = sb + (u % NST) * STAGE_B;
        int k0 = u * TBK;
        #pragma unroll
        for (int i = 0; i < 4; i++) {
            int r = ar + i * 32;
            cpa16(st + r * (A_STR * 4) + akc * 16,
                  A + (row0 + r) * DD + k0 + akc * 4);
        }
        uint32_t bbase = st + A_TILE_B;
        #pragma unroll
        for (int i = 0; i < 4; i++) {
            int k = bk + i * 8;
            cpa16(bbase + k * (B_STR * 4) + bnc * 16,
                  W + (size_t)(k0 + k) * DD + col0 + bnc * 4);
        }
    };

    float acc[4][4][4];
    #pragma unroll
    for (int i = 0; i < 4; i++)
        #pragma unroll
        for (int j = 0; j < 4; j++)
            #pragma unroll
            for (int k = 0; k < 4; k++) acc[i][j][k] = 0.f;

    load_stage(0); CPA_COMMIT();
    load_stage(1); CPA_COMMIT();

    for (int t = 0; t < NKT; t++) {
        CPA_WAIT1();
        __syncthreads();
        if (t + 2 < NKT) load_stage(t + 2);
        CPA_COMMIT();
        const float* sA = (const float*)(smem + (t % NST) * STAGE_B);
        const float* sB = (const float*)(smem + (t % NST) * STAGE_B + A_TILE_B);
        #pragma unroll
        for (int ks = 0; ks < 4; ks++) {
            int kc = ks * 8 + (lane & 3);
            unsigned a[4][4], b[4][2];
            #pragma unroll
            for (int fm = 0; fm < 4; fm++) {
                int r = wm + fm * 16 + (lane >> 2);
                a[fm][0] = __float_as_uint(sA[r * A_STR + kc]);
                a[fm][1] = __float_as_uint(sA[(r + 8) * A_STR + kc]);
                a[fm][2] = __float_as_uint(sA[r * A_STR + kc + 4]);
                a[fm][3] = __float_as_uint(sA[(r + 8) * A_STR + kc + 4]);
            }
            #pragma unroll
            for (int fn = 0; fn < 4; fn++) {
                int cn = wn + fn * 8 + (lane >> 2);
                b[fn][0] = __float_as_uint(sB[kc * B_STR + cn]);
                b[fn][1] = __float_as_uint(sB[(kc + 4) * B_STR + cn]);
            }
            #pragma unroll
            for (int fm = 0; fm < 4; fm++)
                #pragma unroll
                for (int fn = 0; fn < 4; fn++)
                    mma_tf32(acc[fm][fn], a[fm], b[fn]);
        }
    }

    // epilogue
    const float* sbias = (const float*)(smem + OFF_BIAS);
    #pragma unroll
    for (int fm = 0; fm < 4; fm++) {
        size_t r0 = row0 + wm + fm * 16 + (lane >> 2);
        size_t r1 = r0 + 8;
        #pragma unroll
        for (int fn = 0; fn < 4; fn++) {
            int cl = wn + fn * 8 + 2 * (lane & 3);
            size_t cn = col0 + cl;
            float bx = sbias[cl], by = sbias[cl + 1];
            float v0 = acc[fm][fn][0] + bx;
            float v1 = acc[fm][fn][1] + by;
            float v2 = acc[fm][fn][2] + bx;
            float v3 = acc[fm][fn][3] + by;
            if (act == 1) {
                v0 = 0.5f * v0 * (1.f + erff(v0 * 0.70710678118654752f));
                v1 = 0.5f * v1 * (1.f + erff(v1 * 0.70710678118654752f));
                v2 = 0.5f * v2 * (1.f + erff(v2 * 0.70710678118654752f));
                v3 = 0.5f * v3 * (1.f + erff(v3 * 0.70710678118654752f));
            }
            if (R) {
                float2 ra = *(const float2*)(R + r0 * DD + cn);
                float2 rb = *(const float2*)(R + r1 * DD + cn);
                v0 += ra.x; v1 += ra.y; v2 += rb.x; v3 += rb.y;
            }
            *(float2*)(C + r0 * DD + cn) = make_float2(v0, v1);
            *(float2*)(C + r1 * DD + cn) = make_float2(v2, v3);
        }
    }
}

// ---------------------------------------------------------------------------
// Embedding gather
// ---------------------------------------------------------------------------
__global__ __launch_bounds__(256) void embed_kernel(
    const int* __restrict__ idx, const float* __restrict__ emb,
    float* __restrict__ X)
{
    int i   = blockIdx.x * 256 + threadIdx.x;
    int tok = i / (DD / 4);
    int c4  = i % (DD / 4);
    const float4* src = (const float4*)(emb + (size_t)idx[tok] * DD);
    ((float4*)X)[i] = src[c4];
}

// ---------------------------------------------------------------------------
// Rotary cos/sin table
// ---------------------------------------------------------------------------
__global__ __launch_bounds__(256) void rope_table_kernel(
    float* __restrict__ cosT, float* __restrict__ sinT)
{
    int i = blockIdx.x * 256 + threadIdx.x;
    int j = i & 31;
    int l = i >> 5;
    double inv = pow(10000.0, -(double)(2 * j) / (double)HDIM);
    double fr  = (double)l * inv;
    cosT[i] = (float)cos(fr);
    sinT[i] = (float)sin(fr);
}

// ---------------------------------------------------------------------------
// Fused rotary + feature map (R4-proven, one matrix per launch)
// ---------------------------------------------------------------------------
__global__ __launch_bounds__(256) void phi_rot_kernel(
    const float* __restrict__ X, const float* __restrict__ omega,
    const float* __restrict__ cosT, const float* __restrict__ sinT,
    const int* __restrict__ mask, float* __restrict__ PH)
{
    __shared__ float4 som[HDIM * FDIM / 4];
    int tid = threadIdx.x;
    #pragma unroll
    for (int p = 0; p < 2; p++)
        som[tid + p * 256] = ((const float4*)omega)[tid + p * 256];
    __syncthreads();

    int id = blockIdx.x * 256 + tid;
    int n  = id / HH;
    int h  = id % HH;
    int l  = n & (LL - 1);

    float q[HDIM];
    const float4* src = (const float4*)(X + (size_t)n * DD + h * HDIM);
    #pragma unroll
    for (int i = 0; i < HDIM / 4; i++) {
        float4 v = src[i];
        q[i * 4 + 0] = v.x; q[i * 4 + 1] = v.y;
        q[i * 4 + 2] = v.z; q[i * 4 + 3] = v.w;
    }
    #pragma unroll
    for (int j = 0; j < 32; j++) {
        float c = cosT[l * 32 + j];
        float s = sinT[l * 32 + j];
        float x1 = q[j], x2 = q[j + 32];
        q[j]      = x1 * c - x2 * s;
        q[j + 32] = x2 * c + x1 * s;
    }
    float m = mask ? (float)mask[n] : 1.0f;

    float4* out = (float4*)(PH + (size_t)id * FDIM);
    #pragma unroll
    for (int f4 = 0; f4 < FDIM / 4; f4++) {
        float4 acc = make_float4(0.f, 0.f, 0.f, 0.f);
        #pragma unroll
        for (int d = 0; d < HDIM; d++) {
            float4 w = som[d * 8 + f4];
            acc.x += q[d] * w.x; acc.y += q[d] * w.y;
            acc.z += q[d] * w.z; acc.w += q[d] * w.w;
        }
        acc.x = fmaxf(acc.x, 0.f) * m; acc.y = fmaxf(acc.y, 0.f) * m;
        acc.z = fmaxf(acc.z, 0.f) * m; acc.w = fmaxf(acc.w, 0.f) * m;
        out[f4] = acc;
    }
}

// ---------------------------------------------------------------------------
// KV partial reduction: 4 L-chunks per (b,h), deterministic partial buffers
// ---------------------------------------------------------------------------
__global__ __launch_bounds__(256) void kv_part_kernel(
    const float* __restrict__ PHK, const float* __restrict__ V,
    float* __restrict__ KVP, float* __restrict__ KSP)
{
    __shared__ float sph[32 * FDIM];
    __shared__ float sv [32 * HDIM];
    int bh = blockIdx.x;
    int ch = blockIdx.y;
    int b  = bh / HH;
    int h  = bh % HH;
    int tid = threadIdx.x;
    int f  = tid & 31;
    int dg = tid >> 5;
    float acc[8] = {0.f,0.f,0.f,0.f,0.f,0.f,0.f,0.f};
    float sacc = 0.f;

    int rA  = tid >> 3, cA = (tid & 7) * 4;
    int lbeg = ch * (LL / KVCH), lend = lbeg + LL / KVCH;
    for (int l0 = lbeg; l0 < lend; l0 += 32) {
        *(float4*)&sph[rA * FDIM + cA] =
            *(const float4*)(PHK + ((size_t)(b * LL + l0 + rA) * HH + h) * FDIM + cA);
        #pragma unroll
        for (int p = 0; p < 2; p++) {
            int ii = tid + p * 256;
            int rr = ii >> 4, cc = (ii & 15) * 4;
            *(float4*)&sv[rr * HDIM + cc] =
                *(const float4*)(V + (size_t)(b * LL + l0 + rr) * DD + h * HDIM + cc);
        }
        __syncthreads();
        #pragma unroll 8
        for (int r = 0; r < 32; r++) {
            float ph = sph[r * FDIM + f];
            sacc += ph;
            float4 v0 = *(const float4*)&sv[r * HDIM + dg * 8];
            float4 v1 = *(const float4*)&sv[r * HDIM + dg * 8 + 4];
            acc[0] += ph * v0.x; acc[1] += ph * v0.y;
            acc[2] += ph * v0.z; acc[3] += ph * v0.w;
            acc[4] += ph * v1.x; acc[5] += ph * v1.y;
            acc[6] += ph * v1.z; acc[7] += ph * v1.w;
        }
        __syncthreads();
    }
    float* dst = KVP + (((size_t)ch * NBH + bh) * FDIM + f) * HDIM + dg * 8;
    #pragma unroll
    for (int jj = 0; jj < 8; jj++) dst[jj] = acc[jj];
    if (dg == 0) KSP[((size_t)ch * NBH + bh) * FDIM + f] = sacc;
}

__global__ __launch_bounds__(256) void kv_reduce_kernel(
    const float* __restrict__ KVP, const float* __restrict__ KSP,
    float* __restrict__ KV, float* __restrict__ KSUM)
{
    int i = blockIdx.x * 256 + threadIdx.x;
    const int NKV = NBH * FDIM * HDIM;   // 393216
    if (i < NKV) {
        float s = KVP[i] + KVP[NKV + i] + KVP[2 * NKV + i] + KVP[3 * NKV + i];
        KV[i] = s;
    }
    if (i < NBH * FDIM) {
        const int NS = NBH * FDIM;
        KSUM[i] = KSP[i] + KSP[NS + i] + KSP[2 * NS + i] + KSP[3 * NS + i];
    }
}

// ---------------------------------------------------------------------------
// Attention output
// ---------------------------------------------------------------------------
__global__ __launch_bounds__(256) void attn_out_kernel(
    const float* __restrict__ PHQ, const float* __restrict__ KV,
    const float* __restrict__ KSUM, float* __restrict__ Y)
{
    __shared__ float4 skv[FDIM * HDIM / 4];
    __shared__ float  sks[FDIM];
    int bh  = blockIdx.y;
    int tid = threadIdx.x;
    #pragma unroll
    for (int p = 0; p < 2; p++)
        skv[tid + p * 256] = ((const float4*)(KV + (size_t)bh * FDIM * HDIM))[tid + p * 256];
    if (tid < FDIM) sks[tid] = KSUM[bh * FDIM + tid];
    __syncthreads();

    int b = bh / HH, h = bh % HH;
    size_t n = (size_t)b * LL + blockIdx.x * 256 + tid;

    float ph[FDIM];
    const float4* src = (const float4*)(PHQ + (n * HH + h) * FDIM);
    #pragma unroll
    for (int i = 0; i < FDIM / 4; i++) {
        float4 v = src[i];
        ph[i * 4 + 0] = v.x; ph[i * 4 + 1] = v.y;
        ph[i * 4 + 2] = v.z; ph[i * 4 + 3] = v.w;
    }
    float den = ATTN_EPS;
    #pragma unroll
    for (int fI = 0; fI < FDIM; fI++) den += ph[fI] * sks[fI];
    float z = 1.0f / den;

    float4* outp = (float4*)(Y + n * DD + h * HDIM);
    #pragma unroll
    for (int d4 = 0; d4 < HDIM / 4; d4++) {
        float4 acc = make_float4(0.f, 0.f, 0.f, 0.f);
        #pragma unroll
        for (int fI = 0; fI < FDIM; fI++) {
            float4 kvv = skv[fI * 16 + d4];
            acc.x += ph[fI] * kvv.x; acc.y += ph[fI] * kvv.y;
            acc.z += ph[fI] * kvv.z; acc.w += ph[fI] * kvv.w;
        }
        acc.x *= z; acc.y *= z; acc.z *= z; acc.w *= z;
        outp[d4] = acc;
    }
}

// ---------------------------------------------------------------------------
// One-pass LayerNorm: 192 threads, float4, warp-shuffle reduce
// ---------------------------------------------------------------------------
__global__ __launch_bounds__(192) void ln_kernel(
    const float* __restrict__ in, const float* __restrict__ g,
    const float* __restrict__ b, float* __restrict__ out)
{
    __shared__ float ws[6], ws2[6], smv[2];
    size_t row = blockIdx.x;
    int tid = threadIdx.x;
    int lane = tid & 31, wid = tid >> 5;

    float4 v = ((const float4*)(in + row * DD))[tid];
    float s  = v.x + v.y + v.z + v.w;
    float s2 = v.x * v.x + v.y * v.y + v.z * v.z + v.w * v.w;
    #pragma unroll
    for (int off = 16; off > 0; off >>= 1) {
        s  += __shfl_xor_sync(0xFFFFFFFF, s,  off);
        s2 += __shfl_xor_sync(0xFFFFFFFF, s2, off);
    }
    if (lane == 0) { ws[wid] = s; ws2[wid] = s2; }
    __syncthreads();
    if (tid < 32) {
        float a  = (lane < 6) ? ws[lane]  : 0.f;
        float a2 = (lane < 6) ? ws2[lane] : 0.f;
        #pragma unroll
        for (int off = 4; off > 0; off >>= 1) {
            a  += __shfl_xor_sync(0xFFFFFFFF, a,  off);
            a2 += __shfl_xor_sync(0xFFFFFFFF, a2, off);
        }
        if (lane == 0) {
            float mu = a * (1.0f / DD);
            smv[0] = mu;
            smv[1] = rsqrtf(a2 * (1.0f / DD) - mu * mu + LN_EPS);
        }
    }
    __syncthreads();
    float mu = smv[0], rstd = smv[1];
    float4 gg = ((const float4*)g)[tid];
    float4 bb = ((const float4*)b)[tid];
    float4 o;
    o.x = (v.x - mu) * rstd * gg.x + bb.x;
    o.y = (v.y - mu) * rstd * gg.y + bb.y;
    o.z = (v.z - mu) * rstd * gg.z + bb.z;
    o.w = (v.w - mu) * rstd * gg.w + bb.w;
    ((float4*)(out + row * DD))[tid] = o;
}

// ---------------------------------------------------------------------------
// Host orchestration
// ---------------------------------------------------------------------------
extern "C" void kernel_launch(void* const* d_in, const int* in_sizes, int n_in,
                              void* d_out, int out_size)
{
    const int*   idx     = (const int*)  d_in[0];
    const int*   mask    = (const int*)  d_in[1];
    const float* tok_emb = (const float*)d_in[2];
    const float* Wq = (const float*)d_in[3];
    const float* bq = (const float*)d_in[4];
    const float* Wk = (const float*)d_in[5];
    const float* bk = (const float*)d_in[6];
    const float* Wv = (const float*)d_in[7];
    const float* bv = (const float*)d_in[8];
    const float* Wo = (const float*)d_in[9];
    const float* bo = (const float*)d_in[10];
    const float* om = (const float*)d_in[11];
    const float* W1 = (const float*)d_in[12];
    const float* b1 = (const float*)d_in[13];
    const float* W2 = (const float*)d_in[14];
    const float* b2 = (const float*)d_in[15];
    const float* g1 = (const float*)d_in[16];
    const float* be1= (const float*)d_in[17];
    const float* g2 = (const float*)d_in[18];
    const float* be2= (const float*)d_in[19];
    const float* gf = (const float*)d_in[20];
    const float* bf = (const float*)d_in[21];
    float* out = (float*)d_out;

    float *X, *Y, *Q, *K, *V, *PHQ, *PHK, *KV, *KSUM, *KVP, *KSP, *COS, *SIN;
    cudaGetSymbolAddress((void**)&X,    g_X);
    cudaGetSymbolAddress((void**)&Y,    g_Y);
    cudaGetSymbolAddress((void**)&Q,    g_Q);
    cudaGetSymbolAddress((void**)&K,    g_K);
    cudaGetSymbolAddress((void**)&V,    g_V);
    cudaGetSymbolAddress((void**)&PHQ,  g_PHQ);
    cudaGetSymbolAddress((void**)&PHK,  g_PHK);
    cudaGetSymbolAddress((void**)&KV,   g_KV);
    cudaGetSymbolAddress((void**)&KSUM, g_KSUM);
    cudaGetSymbolAddress((void**)&KVP,  g_KVP);
    cudaGetSymbolAddress((void**)&KSP,  g_KSP);
    cudaGetSymbolAddress((void**)&COS,  g_COS);
    cudaGetSymbolAddress((void**)&SIN,  g_SIN);

    cudaFuncSetAttribute(pgemm_kernel,
                         cudaFuncAttributeMaxDynamicSharedMemorySize, SMEM_GEMM);

    const size_t WMAT = (size_t)DD * DD;
    dim3 gGrid(DD / TN, NTOK / TM);   // (6, 256)

    rope_table_kernel<<<(LL * 32) / 256, 256>>>(COS, SIN);
    embed_kernel<<<(NTOK * DD / 4) / 256, 256>>>(idx, tok_emb, X);

    for (int i = 0; i < NLAYER; i++) {
        const float* om_i = om + (size_t)i * HDIM * FDIM;

        pgemm_kernel<<<gGrid, 256, SMEM_GEMM>>>(X, Wq + i * WMAT, bq + i * DD, nullptr, Q, 0);
        pgemm_kernel<<<gGrid, 256, SMEM_GEMM>>>(X, Wk + i * WMAT, bk + i * DD, nullptr, K, 0);
        pgemm_kernel<<<gGrid, 256, SMEM_GEMM>>>(X, Wv + i * WMAT, bv + i * DD, nullptr, V, 0);

        phi_rot_kernel<<<(NTOK * HH) / 256, 256>>>(Q, om_i, COS, SIN, nullptr, PHQ);
        phi_rot_kernel<<<(NTOK * HH) / 256, 256>>>(K, om_i, COS, SIN, mask,    PHK);

        kv_part_kernel<<<dim3(NBH, KVCH), 256>>>(PHK, V, KVP, KSP);
        kv_reduce_kernel<<<(NBH * FDIM * HDIM) / 256, 256>>>(KVP, KSP, KV, KSUM);

        attn_out_kernel<<<dim3(LL / 256, NBH), 256>>>(PHQ, KV, KSUM, Y);

        // X = Y @ Wo + bo + X
        pgemm_kernel<<<gGrid, 256, SMEM_GEMM>>>(Y, Wo + i * WMAT, bo + i * DD, X, X, 0);
        ln_kernel<<<NTOK, 192>>>(X, g1 + i * DD, be1 + i * DD, X);
        // Q = gelu(X @ W1 + b1)
        pgemm_kernel<<<gGrid, 256, SMEM_GEMM>>>(X, W1 + i * WMAT, b1 + i * DD, nullptr, Q, 1);
        // Y = Q @ W2 + b2 + X
        pgemm_kernel<<<gGrid, 256, SMEM_GEMM>>>(Q, W2 + i * WMAT, b2 + i * DD, X, Y, 0);
        ln_kernel<<<NTOK, 192>>>(Y, g2 + i * DD, be2 + i * DD, X);
    }

    ln_kernel<<<NTOK, 192>>>(X, gf, bf, out);
}